// round 15
// baseline (speedup 1.0000x reference)
#include <cuda_runtime.h>
#include <cuda_bf16.h>
#include <math_constants.h>
#include <cstdint>

// Problem constants (fixed by the dataset)
#define BATCH   32
#define SEQ     512
#define DMODEL  512
#define HEADS   8
#define DKH     64
#define MROWS   (BATCH * SEQ)          // 16384

// ---------------------------------------------------------------------------
// Scratch (allocation-free rule: __device__ globals)
// ---------------------------------------------------------------------------
__device__ float g_Qp[MROWS * DMODEL];
__device__ float g_Kp[MROWS * DMODEL];
__device__ float g_Vp[MROWS * DMODEL];
__device__ float g_AO[MROWS * DMODEL];
__device__ __nv_bfloat16 g_Ahi[MROWS * DMODEL];
__device__ __nv_bfloat16 g_Alo[MROWS * DMODEL];
__device__ __nv_bfloat16 g_Wthi[DMODEL * DMODEL];
__device__ __nv_bfloat16 g_Wtlo[DMODEL * DMODEL];

// f32x2 packed-FMA helpers (Blackwell FFMA2; exact IEEE fp32 per lane)
#define FMA2(acc, a, b)                                                      \
    asm("fma.rn.f32x2 %0, %1, %2, %0;" : "+l"(acc) : "l"(a), "l"(b))
#define SPLAT2(dst, fu)                                                      \
    asm("mov.b64 %0, {%1,%1};" : "=l"(dst) : "r"(fu))
#define UNPK2(lo, hi, src)                                                   \
    asm("mov.b64 {%0,%1}, %2;" : "=r"(lo), "=r"(hi) : "l"(src))

// order-preserving float<->u32 map (monotone increasing)
__device__ __forceinline__ uint32_t ford(float f) {
    uint32_t b = __float_as_uint(f);
    return (b & 0x80000000u) ? ~b : (b | 0x80000000u);
}
__device__ __forceinline__ float ford_inv(uint32_t u) {
    uint32_t b = (u & 0x80000000u) ? (u & 0x7fffffffu) : ~u;
    return __uint_as_float(b);
}

// ---------------------------------------------------------------------------
// Fused conversion kernel:
//   blocks [0,256):  transpose+split weights Wt[n][k] = W[k][n] (hi/lo bf16)
//   blocks [256,..): split fp32 activations into hi/lo bf16
// ---------------------------------------------------------------------------
__global__ void __launch_bounds__(256)
conv_fused(const float4* __restrict__ X, const float* __restrict__ W,
           uint2* __restrict__ Hi, uint2* __restrict__ Lo,
           __nv_bfloat16* __restrict__ Thi, __nv_bfloat16* __restrict__ Tlo,
           int n4)
{
    __shared__ float s[32][33];
    const int tid = threadIdx.x;

    if (blockIdx.x < 256) {
        const int bx = blockIdx.x & 15, by = blockIdx.x >> 4;
        const int tx = tid & 31, ty = tid >> 5;
#pragma unroll
        for (int i = 0; i < 32; i += 8)
            s[ty + i][tx] = W[(by * 32 + ty + i) * DMODEL + bx * 32 + tx];
        __syncthreads();
#pragma unroll
        for (int i = 0; i < 32; i += 8) {
            float x = s[tx][ty + i];
            int n = bx * 32 + ty + i;
            int k = by * 32 + tx;
            __nv_bfloat16 h = __float2bfloat16(x);
            Thi[n * DMODEL + k] = h;
            Tlo[n * DMODEL + k] = __float2bfloat16(x - __bfloat162float(h));
        }
        return;
    }

    const int i = (blockIdx.x - 256) * 256 + tid;
    if (i >= n4) return;
    float4 x = X[i];
    __nv_bfloat16 h0 = __float2bfloat16(x.x);
    __nv_bfloat16 h1 = __float2bfloat16(x.y);
    __nv_bfloat16 h2 = __float2bfloat16(x.z);
    __nv_bfloat16 h3 = __float2bfloat16(x.w);
    __nv_bfloat16 l0 = __float2bfloat16(x.x - __bfloat162float(h0));
    __nv_bfloat16 l1 = __float2bfloat16(x.y - __bfloat162float(h1));
    __nv_bfloat16 l2 = __float2bfloat16(x.z - __bfloat162float(h2));
    __nv_bfloat16 l3 = __float2bfloat16(x.w - __bfloat162float(h3));
    uint2 uh, ul;
    uh.x = ((uint32_t)__bfloat16_as_ushort(h1) << 16) | __bfloat16_as_ushort(h0);
    uh.y = ((uint32_t)__bfloat16_as_ushort(h3) << 16) | __bfloat16_as_ushort(h2);
    ul.x = ((uint32_t)__bfloat16_as_ushort(l1) << 16) | __bfloat16_as_ushort(l0);
    ul.y = ((uint32_t)__bfloat16_as_ushort(l3) << 16) | __bfloat16_as_ushort(l2);
    Hi[i] = uh;
    Lo[i] = ul;
}

// ---------------------------------------------------------------------------
// fp32 SGEMM with packed f32x2 FMA; conflict-free B fragments (R5 layout)
// + register prefetch (R11 WIN). gridDim.z selects Q or K projection.
// ---------------------------------------------------------------------------
__global__ void __launch_bounds__(256, 2)
sgemm_bias_x2_qk(const float* __restrict__ A0, const float* __restrict__ W0,
                 const float* __restrict__ bias0, float* __restrict__ C0,
                 const float* __restrict__ A1, const float* __restrict__ W1,
                 const float* __restrict__ bias1, float* __restrict__ C1)
{
    __shared__ float As[8][128];   // transposed A tile: As[k][m]
    __shared__ float Bs[8][128];   // Bs[k][n]

    const float* A    = blockIdx.z ? A1 : A0;
    const float* W    = blockIdx.z ? W1 : W0;
    const float* bias = blockIdx.z ? bias1 : bias0;
    float*       C    = blockIdx.z ? C1 : C0;

    const int tid = threadIdx.x;
    const int bm = blockIdx.y * 128;
    const int bn = blockIdx.x * 128;
    const int tx = tid & 15;
    const int ty = tid >> 4;

    const int arow = tid >> 1;
    const int ac4  = (tid & 1) << 2;
    const int brow = tid >> 5;
    const int bc4  = (tid & 31) << 2;

    const float* Ap = A + (size_t)(bm + arow) * DMODEL + ac4;
    const float* Wp = W + (size_t)brow * DMODEL + (bn + bc4);

    unsigned long long acc2[8][4];
#pragma unroll
    for (int i = 0; i < 8; i++)
#pragma unroll
        for (int j = 0; j < 4; j++) acc2[i][j] = 0ull;

    float4 av = *(const float4*)Ap;
    float4 bv = *(const float4*)Wp;

    for (int kt = 0; kt < DMODEL / 8; kt++) {
        __syncthreads();
        As[ac4 + 0][arow] = av.x;
        As[ac4 + 1][arow] = av.y;
        As[ac4 + 2][arow] = av.z;
        As[ac4 + 3][arow] = av.w;
        *(float4*)&Bs[brow][bc4] = bv;
        __syncthreads();

        if (kt + 1 < DMODEL / 8) {   // register prefetch of next tile
            av = *(const float4*)(Ap + (kt + 1) * 8);
            bv = *(const float4*)(Wp + (size_t)(kt + 1) * 8 * DMODEL);
        }

#pragma unroll
        for (int k = 0; k < 8; k++) {
            float a[8];
            *(float4*)&a[0] = *(const float4*)&As[k][ty * 8];
            *(float4*)&a[4] = *(const float4*)&As[k][ty * 8 + 4];
            unsigned long long b2[4];
#pragma unroll
            for (int j = 0; j < 4; j++)
                b2[j] = *(const unsigned long long*)&Bs[k][2 * tx + 32 * j];
            unsigned long long a2[8];
#pragma unroll
            for (int i = 0; i < 8; i++) SPLAT2(a2[i], __float_as_uint(a[i]));
#pragma unroll
            for (int i = 0; i < 8; i++)
#pragma unroll
                for (int j = 0; j < 4; j++)
                    FMA2(acc2[i][j], a2[i], b2[j]);
        }
    }

#pragma unroll
    for (int i = 0; i < 8; i++) {
        float* crow = C + (size_t)(bm + ty * 8 + i) * DMODEL + bn;
#pragma unroll
        for (int j = 0; j < 4; j++) {
            const int col = 2 * tx + 32 * j;
            unsigned lo, hi;
            UNPK2(lo, hi, acc2[i][j]);
            float2 o;
            o.x = __uint_as_float(lo) + bias[bn + col];
            o.y = __uint_as_float(hi) + bias[bn + col + 1];
            *(float2*)(crow + col) = o;
        }
    }
}

// ---------------------------------------------------------------------------
// Tensor-core GEMM (bf16 3-MMA split, legacy mma.sync) — V and output
// projections. Proven R2/R5.
// ---------------------------------------------------------------------------
#define GBM 128
#define GBN 128
#define GBK 32
#define GSTR 40
#define GSTAGE 20480
#define GNK (DMODEL / GBK)

#define MMA16816(c, a, b0, b1)                                               \
    asm volatile(                                                            \
        "mma.sync.aligned.m16n8k16.row.col.f32.bf16.bf16.f32 "               \
        "{%0,%1,%2,%3},{%4,%5,%6,%7},{%8,%9},{%0,%1,%2,%3};"                 \
        : "+f"(c[0]), "+f"(c[1]), "+f"(c[2]), "+f"(c[3])                     \
        : "r"(a[0]), "r"(a[1]), "r"(a[2]), "r"(a[3]), "r"(b0), "r"(b1))

#define CPA16(sdst, gsrc)                                                    \
    {                                                                        \
        uint32_t _d = (uint32_t)__cvta_generic_to_shared(sdst);              \
        asm volatile("cp.async.cg.shared.global [%0], [%1], 16;"             \
                     :: "r"(_d), "l"(gsrc));                                 \
    }

__global__ void __launch_bounds__(256, 2)
gemm_bf16x3(const __nv_bfloat16* __restrict__ Ahi,
            const __nv_bfloat16* __restrict__ Alo,
            const __nv_bfloat16* __restrict__ Bthi,
            const __nv_bfloat16* __restrict__ Btlo,
            const float* __restrict__ bias, float* __restrict__ C)
{
    extern __shared__ __nv_bfloat16 sm[];
    const int tid = threadIdx.x;
    const int lane = tid & 31;
    const int g = lane >> 2;
    const int tg = lane & 3;
    const int wid = tid >> 5;
    const int warp_m = wid >> 1;
    const int warp_n = wid & 1;
    const int bm = blockIdx.y * GBM;
    const int bn = blockIdx.x * GBN;

    float acc[2][8][4];
#pragma unroll
    for (int mt = 0; mt < 2; mt++)
#pragma unroll
        for (int nt = 0; nt < 8; nt++)
#pragma unroll
            for (int j = 0; j < 4; j++) acc[mt][nt][j] = 0.0f;

    const int ld_row = tid >> 2;
    const int ld_q   = tid & 3;

    const __nv_bfloat16* gAh = Ahi + (size_t)bm * DMODEL;
    const __nv_bfloat16* gAl = Alo + (size_t)bm * DMODEL;
    const __nv_bfloat16* gBh = Bthi + (size_t)bn * DMODEL;
    const __nv_bfloat16* gBl = Btlo + (size_t)bn * DMODEL;

    auto issue_stage = [&](int kt) {
        const int k0 = kt * GBK;
        __nv_bfloat16* base = sm + (kt & 1) * GSTAGE;
#pragma unroll
        for (int cc = 0; cc < 2; cc++) {
            const int row = ld_row + cc * 64;
            const int soff = row * GSTR + ld_q * 8;
            const size_t goff = (size_t)row * DMODEL + k0 + ld_q * 8;
            CPA16(base + soff,         gAh + goff);
            CPA16(base + 5120 + soff,  gAl + goff);
            CPA16(base + 10240 + soff, gBh + goff);
            CPA16(base + 15360 + soff, gBl + goff);
        }
        asm volatile("cp.async.commit_group;");
    };

    issue_stage(0);

    for (int kt = 0; kt < GNK; kt++) {
        asm volatile("cp.async.wait_group 0;" ::: "memory");
        __syncthreads();
        if (kt + 1 < GNK) issue_stage(kt + 1);

        const __nv_bfloat16* sa_hi = sm + (kt & 1) * GSTAGE;
        const __nv_bfloat16* sa_lo = sa_hi + 5120;
        const __nv_bfloat16* sb_hi = sa_hi + 10240;
        const __nv_bfloat16* sb_lo = sa_hi + 15360;

#pragma unroll
        for (int ks = 0; ks < 2; ks++) {
            const int kb = ks * 16 + tg * 2;
            uint32_t ah[2][4], al[2][4];
#pragma unroll
            for (int mt = 0; mt < 2; mt++) {
                const int r = warp_m * 32 + mt * 16 + g;
                const __nv_bfloat16* pa = sa_hi + r * GSTR + kb;
                ah[mt][0] = *(const uint32_t*)(pa);
                ah[mt][1] = *(const uint32_t*)(pa + 8 * GSTR);
                ah[mt][2] = *(const uint32_t*)(pa + 8);
                ah[mt][3] = *(const uint32_t*)(pa + 8 * GSTR + 8);
                const __nv_bfloat16* pl = sa_lo + r * GSTR + kb;
                al[mt][0] = *(const uint32_t*)(pl);
                al[mt][1] = *(const uint32_t*)(pl + 8 * GSTR);
                al[mt][2] = *(const uint32_t*)(pl + 8);
                al[mt][3] = *(const uint32_t*)(pl + 8 * GSTR + 8);
            }
#pragma unroll
            for (int nt = 0; nt < 8; nt++) {
                const int n = warp_n * 64 + nt * 8 + g;
                const __nv_bfloat16* pb = sb_hi + n * GSTR + kb;
                uint32_t bh0 = *(const uint32_t*)(pb);
                uint32_t bh1 = *(const uint32_t*)(pb + 8);
                const __nv_bfloat16* pbl = sb_lo + n * GSTR + kb;
                uint32_t bl0 = *(const uint32_t*)(pbl);
                uint32_t bl1 = *(const uint32_t*)(pbl + 8);
#pragma unroll
                for (int mt = 0; mt < 2; mt++) {
                    MMA16816(acc[mt][nt], ah[mt], bh0, bh1);
                    MMA16816(acc[mt][nt], ah[mt], bl0, bl1);
                    MMA16816(acc[mt][nt], al[mt], bh0, bh1);
                }
            }
        }
    }

#pragma unroll
    for (int mt = 0; mt < 2; mt++) {
        const int r0 = bm + warp_m * 32 + mt * 16 + g;
#pragma unroll
        for (int nt = 0; nt < 8; nt++) {
            const int col = bn + warp_n * 64 + nt * 8 + tg * 2;
            const float bx = bias[col];
            const float by = bias[col + 1];
            float2 v0 = make_float2(acc[mt][nt][0] + bx, acc[mt][nt][1] + by);
            float2 v1 = make_float2(acc[mt][nt][2] + bx, acc[mt][nt][3] + by);
            *(float2*)&C[(size_t)r0 * DMODEL + col] = v0;
            *(float2*)&C[(size_t)(r0 + 8) * DMODEL + col] = v1;
        }
    }
}

// ---------------------------------------------------------------------------
// Sparse causal attention (R14 WIN): 4 rows/warp, 128-thread blocks,
// 5 CTAs/SM, conflict-free key-major loader, REDUX top-k per row-pair.
// R15: 1/sqrt(DK)=0.125 folded into the q smem store (power-of-two scale,
// bitwise-identical scores) — deletes the mask-phase multiplies.
// ---------------------------------------------------------------------------
#define AT_ROWS 16
#define KTILE   128
#define KPAD    128
#define MAXK    5
#define NEGINF  (-CUDART_INF_F)

__global__ void __launch_bounds__(128, 5)
attn_sparse(const float* __restrict__ Q, const float* __restrict__ K,
            const float* __restrict__ V, const int* __restrict__ kidx_p,
            float* __restrict__ O)
{
    __shared__ float ks[DKH][KPAD];        // 32 KB transposed K tile
    __shared__ float qs2[AT_ROWS][128];    // 8 KB duplicated q rows

    const int bh = blockIdx.y;
    const int b  = bh >> 3;
    const int h  = bh & 7;
    const int row_base = blockIdx.x * AT_ROWS;
    const int tid  = threadIdx.x;          // 0..127
    const int wid  = tid >> 5;             // 0..3
    const int lane = tid & 31;
    const int kk   = *kidx_p;

    const size_t base = ((size_t)b * SEQ) * DMODEL + (size_t)h * DKH;

    // load q rows (pre-scaled by 0.125), duplicated
    for (int i = tid; i < AT_ROWS * DKH; i += 128) {
        const int rr = i >> 6, d = i & 63;
        const float qv =
            Q[base + (size_t)(row_base + rr) * DMODEL + d] * 0.125f;
        unsigned long long q2;
        SPLAT2(q2, __float_as_uint(qv));
        *(unsigned long long*)&qs2[rr][2 * d] = q2;
    }

    const int nkeys = row_base + AT_ROWS - 1;   // strictly-causal: keys j < r
    const int lr0 = wid * 4;                    // 4 rows per warp

    unsigned long long sc2[4][8];
#pragma unroll
    for (int rr = 0; rr < 4; rr++)
#pragma unroll
        for (int p = 0; p < 8; p++) sc2[rr][p] = 0ull;

    // ---- score pass: QK^T over key tiles ----
#pragma unroll
    for (int tt = 0; tt < 4; tt++) {
        const int t0k = tt << 7;
        if (t0k >= nkeys) break;
        const int tl = min(KTILE, nkeys - t0k);
        __syncthreads();
        // loader: thread tid owns key=tid, loads its whole 64-d row
        {
            const float* krow = &K[base + (size_t)(t0k + tid) * DMODEL];
            const bool ok = tid < tl;
#pragma unroll
            for (int p = 0; p < 16; p++) {
                const int d4 = p << 2;
                float4 kv = ok ? *(const float4*)(krow + d4)
                               : make_float4(0.f, 0.f, 0.f, 0.f);
                ks[d4 + 0][tid] = kv.x;
                ks[d4 + 1][tid] = kv.y;
                ks[d4 + 2][tid] = kv.z;
                ks[d4 + 3][tid] = kv.w;
            }
        }
        __syncthreads();
#pragma unroll 4
        for (int d = 0; d < DKH; d += 2) {
            const ulonglong2 kva = *(const ulonglong2*)&ks[d][lane << 2];
            const ulonglong2 kvb = *(const ulonglong2*)&ks[d + 1][lane << 2];
#pragma unroll
            for (int rr = 0; rr < 4; rr++) {
                const ulonglong2 qp =
                    *(const ulonglong2*)&qs2[lr0 + rr][2 * d]; // {qd,qd+1}dup
                FMA2(sc2[rr][tt * 2 + 0], qp.x, kva.x);
                FMA2(sc2[rr][tt * 2 + 1], qp.x, kva.y);
                FMA2(sc2[rr][tt * 2 + 0], qp.y, kvb.x);
                FMA2(sc2[rr][tt * 2 + 1], qp.y, kvb.y);
            }
        }
    }

    // ---- per row-pair: unpack, mask, REDUX top-k, streamed PV ----
#pragma unroll
    for (int pp = 0; pp < 2; pp++) {
        const int r0g = row_base + lr0 + pp * 2;
        const int r1g = r0g + 1;

        float sc[2][16];
#pragma unroll
        for (int q2i = 0; q2i < 2; q2i++)
#pragma unroll
            for (int p = 0; p < 8; p++) {
                unsigned lo, hi;
                UNPK2(lo, hi, sc2[pp * 2 + q2i][p]);
                sc[q2i][p * 2]     = __uint_as_float(lo);
                sc[q2i][p * 2 + 1] = __uint_as_float(hi);
            }

        // mask invalid keys (scale already folded into q)
#pragma unroll
        for (int rr = 0; rr < 2; rr++) {
            const int r = r0g + rr;
#pragma unroll
            for (int s = 0; s < 16; s++) {
                const int j = ((s >> 2) << 7) + (lane << 2) + (s & 3);
                if (j >= r) sc[rr][s] = NEGINF;
            }
        }

        // extraction: nex = min(r, kk) warp maxima per row
        const int nex0 = min(r0g, kk);
        const int nex1 = min(r1g, kk);
        const int nexm = min(max(nex0, nex1), MAXK);

        float lm0 = NEGINF, lm1 = NEGINF;
        int   sl0 = 0, sl1 = 0;
        unsigned rem0 = 0, rem1 = 0;
#pragma unroll
        for (int s = 0; s < 16; s++) {
            if (sc[0][s] > lm0) { lm0 = sc[0][s]; sl0 = s; }
            if (sc[1][s] > lm1) { lm1 = sc[1][s]; sl1 = s; }
        }

        float ev0[MAXK], ev1[MAXK];
        int   ej0[MAXK], ej1[MAXK];
#pragma unroll
        for (int e = 0; e < MAXK; e++) {
            ev0[e] = NEGINF; ev1[e] = NEGINF; ej0[e] = 0; ej1[e] = 0;
        }

#pragma unroll
        for (int e = 0; e < MAXK; e++) {
            if (e < nexm) {
                const uint32_t u0 = ford(lm0);
                const uint32_t u1 = ford(lm1);
                const uint32_t mx0 = __reduce_max_sync(0xffffffffu, u0);
                const uint32_t mx1 = __reduce_max_sync(0xffffffffu, u1);
                const unsigned bl0 = __ballot_sync(0xffffffffu, u0 == mx0);
                const unsigned bl1 = __ballot_sync(0xffffffffu, u1 == mx1);
                const int own0 = __ffs(bl0) - 1;
                const int own1 = __ffs(bl1) - 1;
                ev0[e] = ford_inv(mx0);
                ev1[e] = ford_inv(mx1);
                const int jid0 = ((sl0 >> 2) << 7) + (lane << 2) + (sl0 & 3);
                const int jid1 = ((sl1 >> 2) << 7) + (lane << 2) + (sl1 & 3);
                ej0[e] = __shfl_sync(0xffffffffu, jid0, own0);
                ej1[e] = __shfl_sync(0xffffffffu, jid1, own1);
                if (lane == own0) {
                    rem0 |= 1u << sl0;
                    lm0 = NEGINF; sl0 = 0;
#pragma unroll
                    for (int s = 0; s < 16; s++) {
                        const float v = ((rem0 >> s) & 1u) ? NEGINF : sc[0][s];
                        if (v > lm0) { lm0 = v; sl0 = s; }
                    }
                }
                if (lane == own1) {
                    rem1 |= 1u << sl1;
                    lm1 = NEGINF; sl1 = 0;
#pragma unroll
                    for (int s = 0; s < 16; s++) {
                        const float v = ((rem1 >> s) & 1u) ? NEGINF : sc[1][s];
                        if (v > lm1) { lm1 = v; sl1 = s; }
                    }
                }
            }
        }

        // inline weights + streamed PV (no staging arrays)
        const float m0 = (nex0 > 0) ? ev0[0] : 0.f;
        const float m1 = (nex1 > 0) ? ev1[0] : 0.f;
        float ksum0 = 0.f, ksum1 = 0.f;
#pragma unroll
        for (int e = 0; e < MAXK; e++) {
            if (e < nex0) ksum0 += __expf(ev0[e] - m0);
            if (e < nex1) ksum1 += __expf(ev1[e] - m1);
        }
        const float inv0 = (nex0 > 0) ? 1.0f / ksum0 : 0.f;
        const float inv1 = (nex1 > 0) ? 1.0f / ksum1 : 0.f;

        float o00 = 0.f, o01 = 0.f, o10 = 0.f, o11 = 0.f;
#pragma unroll
        for (int e = 0; e < MAXK; e++) {
            const float w0 = (e < nex0) ? __expf(ev0[e] - m0) * inv0 : 0.f;
            const float w1 = (e < nex1) ? __expf(ev1[e] - m1) * inv1 : 0.f;
            const float* v0p = &V[base + (size_t)ej0[e] * DMODEL];
            const float* v1p = &V[base + (size_t)ej1[e] * DMODEL];
            if (e < nex0) {
                o00 = fmaf(w0, v0p[lane], o00);
                o01 = fmaf(w0, v0p[lane + 32], o01);
            }
            if (e < nex1) {
                o10 = fmaf(w1, v1p[lane], o10);
                o11 = fmaf(w1, v1p[lane + 32], o11);
            }
        }

        O[base + (size_t)r0g * DMODEL + lane]      = o00;
        O[base + (size_t)r0g * DMODEL + lane + 32] = o01;
        O[base + (size_t)r1g * DMODEL + lane]      = o10;
        O[base + (size_t)r1g * DMODEL + lane + 32] = o11;
    }
}

// ---------------------------------------------------------------------------
extern "C" void kernel_launch(void* const* d_in, const int* in_sizes, int n_in,
                              void* d_out, int out_size)
{
    const float* q   = (const float*)d_in[0];
    const float* k   = (const float*)d_in[1];
    const float* v   = (const float*)d_in[2];
    const float* w_q = (const float*)d_in[3];
    const float* b_q = (const float*)d_in[4];
    const float* w_k = (const float*)d_in[5];
    const float* b_k = (const float*)d_in[6];
    const float* w_v = (const float*)d_in[7];
    const float* b_v = (const float*)d_in[8];
    const float* w_o = (const float*)d_in[9];
    const float* b_o = (const float*)d_in[10];
    const int*   kid = (const int*)d_in[11];
    float* out = (float*)d_out;

    float *Qp, *Kp, *Vp, *AO;
    __nv_bfloat16 *Ahi, *Alo, *Wthi, *Wtlo;
    cudaGetSymbolAddress((void**)&Qp, g_Qp);
    cudaGetSymbolAddress((void**)&Kp, g_Kp);
    cudaGetSymbolAddress((void**)&Vp, g_Vp);
    cudaGetSymbolAddress((void**)&AO, g_AO);
    cudaGetSymbolAddress((void**)&Ahi, g_Ahi);
    cudaGetSymbolAddress((void**)&Alo, g_Alo);
    cudaGetSymbolAddress((void**)&Wthi, g_Wthi);
    cudaGetSymbolAddress((void**)&Wtlo, g_Wtlo);

    // One-time setup (statics are init-only, not work guards).
    static cudaStream_t s2 = nullptr;
    static cudaEvent_t ev_fork = nullptr, ev_join = nullptr;
    if (s2 == nullptr) {
        cudaStreamCreateWithFlags(&s2, cudaStreamNonBlocking);
        cudaEventCreateWithFlags(&ev_fork, cudaEventDisableTiming);
        cudaEventCreateWithFlags(&ev_join, cudaEventDisableTiming);
        cudaFuncSetAttribute(gemm_bf16x3,
                             cudaFuncAttributeMaxDynamicSharedMemorySize,
                             2 * GSTAGE * (int)sizeof(__nv_bfloat16));
    }

    const int n4 = MROWS * DMODEL / 4;
    const int cfblk = 256 + (n4 + 255) / 256;     // fused conv grid
    dim3 ggrid(DMODEL / GBN, MROWS / GBM);        // (4, 128)
    dim3 ggrid_qk(DMODEL / 128, MROWS / 128, 2);  // Q and K in one launch
    const int smem = 2 * GSTAGE * (int)sizeof(__nv_bfloat16);

    // ---- fork: V path on s2 (DRAM+tensor), QK on stream 0 (FMA pipe) ----
    cudaEventRecord(ev_fork, 0);
    cudaStreamWaitEvent(s2, ev_fork, 0);

    // s2 branch: V conversion + V projection.
    conv_fused<<<cfblk, 256, 0, s2>>>((const float4*)v, w_v,
                                      (uint2*)Ahi, (uint2*)Alo,
                                      Wthi, Wtlo, n4);
    gemm_bf16x3<<<ggrid, 256, smem, s2>>>(Ahi, Alo, Wthi, Wtlo, b_v, Vp);
    cudaEventRecord(ev_join, s2);

    // stream-0 branch: Q + K projections (exact fp32, packed f32x2 FMA).
    sgemm_bias_x2_qk<<<ggrid_qk, 256>>>(q, w_q, b_q, Qp, k, w_k, b_k, Kp);

    // ---- join, then attention ----
    cudaStreamWaitEvent(0, ev_join, 0);
    dim3 ga(SEQ / AT_ROWS, BATCH * HEADS); // (32, 256)
    attn_sparse<<<ga, 128>>>(Qp, Kp, Vp, kid, AO);

    // Output conversion path (w_o transpose + AO split fused), then proj.
    conv_fused<<<cfblk, 256>>>((const float4*)AO, w_o,
                               (uint2*)Ahi, (uint2*)Alo, Wthi, Wtlo, n4);
    gemm_bf16x3<<<ggrid, 256, smem>>>(Ahi, Alo, Wthi, Wtlo, b_o, out);
}

// round 16
// speedup vs baseline: 1.0306x; 1.0306x over previous
#include <cuda_runtime.h>
#include <cuda_bf16.h>
#include <math_constants.h>
#include <cstdint>

// Problem constants (fixed by the dataset)
#define BATCH   32
#define SEQ     512
#define DMODEL  512
#define HEADS   8
#define DKH     64
#define MROWS   (BATCH * SEQ)          // 16384

// ---------------------------------------------------------------------------
// Scratch (allocation-free rule: __device__ globals)
// ---------------------------------------------------------------------------
__device__ float g_Qp[MROWS * DMODEL];
__device__ float g_Kp[MROWS * DMODEL];
__device__ float g_Vp[MROWS * DMODEL];
__device__ float g_AO[MROWS * DMODEL];
__device__ __nv_bfloat16 g_Ahi[MROWS * DMODEL];
__device__ __nv_bfloat16 g_Alo[MROWS * DMODEL];
__device__ __nv_bfloat16 g_Wthi[DMODEL * DMODEL];
__device__ __nv_bfloat16 g_Wtlo[DMODEL * DMODEL];

// f32x2 packed-FMA helpers (Blackwell FFMA2; exact IEEE fp32 per lane)
#define FMA2(acc, a, b)                                                      \
    asm("fma.rn.f32x2 %0, %1, %2, %0;" : "+l"(acc) : "l"(a), "l"(b))
#define SPLAT2(dst, fu)                                                      \
    asm("mov.b64 %0, {%1,%1};" : "=l"(dst) : "r"(fu))
#define UNPK2(lo, hi, src)                                                   \
    asm("mov.b64 {%0,%1}, %2;" : "=r"(lo), "=r"(hi) : "l"(src))

// order-preserving float<->u32 map (monotone increasing)
__device__ __forceinline__ uint32_t ford(float f) {
    uint32_t b = __float_as_uint(f);
    return (b & 0x80000000u) ? ~b : (b | 0x80000000u);
}
__device__ __forceinline__ float ford_inv(uint32_t u) {
    uint32_t b = (u & 0x80000000u) ? (u & 0x7fffffffu) : ~u;
    return __uint_as_float(b);
}

// ---------------------------------------------------------------------------
// Fused conversion kernel:
//   blocks [0,256):  transpose+split weights Wt[n][k] = W[k][n] (hi/lo bf16)
//   blocks [256,..): split fp32 activations into hi/lo bf16
// ---------------------------------------------------------------------------
__global__ void __launch_bounds__(256)
conv_fused(const float4* __restrict__ X, const float* __restrict__ W,
           uint2* __restrict__ Hi, uint2* __restrict__ Lo,
           __nv_bfloat16* __restrict__ Thi, __nv_bfloat16* __restrict__ Tlo,
           int n4)
{
    __shared__ float s[32][33];
    const int tid = threadIdx.x;

    if (blockIdx.x < 256) {
        const int bx = blockIdx.x & 15, by = blockIdx.x >> 4;
        const int tx = tid & 31, ty = tid >> 5;
#pragma unroll
        for (int i = 0; i < 32; i += 8)
            s[ty + i][tx] = W[(by * 32 + ty + i) * DMODEL + bx * 32 + tx];
        __syncthreads();
#pragma unroll
        for (int i = 0; i < 32; i += 8) {
            float x = s[tx][ty + i];
            int n = bx * 32 + ty + i;
            int k = by * 32 + tx;
            __nv_bfloat16 h = __float2bfloat16(x);
            Thi[n * DMODEL + k] = h;
            Tlo[n * DMODEL + k] = __float2bfloat16(x - __bfloat162float(h));
        }
        return;
    }

    const int i = (blockIdx.x - 256) * 256 + tid;
    if (i >= n4) return;
    float4 x = X[i];
    __nv_bfloat16 h0 = __float2bfloat16(x.x);
    __nv_bfloat16 h1 = __float2bfloat16(x.y);
    __nv_bfloat16 h2 = __float2bfloat16(x.z);
    __nv_bfloat16 h3 = __float2bfloat16(x.w);
    __nv_bfloat16 l0 = __float2bfloat16(x.x - __bfloat162float(h0));
    __nv_bfloat16 l1 = __float2bfloat16(x.y - __bfloat162float(h1));
    __nv_bfloat16 l2 = __float2bfloat16(x.z - __bfloat162float(h2));
    __nv_bfloat16 l3 = __float2bfloat16(x.w - __bfloat162float(h3));
    uint2 uh, ul;
    uh.x = ((uint32_t)__bfloat16_as_ushort(h1) << 16) | __bfloat16_as_ushort(h0);
    uh.y = ((uint32_t)__bfloat16_as_ushort(h3) << 16) | __bfloat16_as_ushort(h2);
    ul.x = ((uint32_t)__bfloat16_as_ushort(l1) << 16) | __bfloat16_as_ushort(l0);
    ul.y = ((uint32_t)__bfloat16_as_ushort(l3) << 16) | __bfloat16_as_ushort(l2);
    Hi[i] = uh;
    Lo[i] = ul;
}

// ---------------------------------------------------------------------------
// fp32 SGEMM with packed f32x2 FMA; conflict-free B fragments (R5 layout)
// + register prefetch (R11 WIN). gridDim.z selects Q or K projection.
// ---------------------------------------------------------------------------
__global__ void __launch_bounds__(256, 2)
sgemm_bias_x2_qk(const float* __restrict__ A0, const float* __restrict__ W0,
                 const float* __restrict__ bias0, float* __restrict__ C0,
                 const float* __restrict__ A1, const float* __restrict__ W1,
                 const float* __restrict__ bias1, float* __restrict__ C1)
{
    __shared__ float As[8][128];   // transposed A tile: As[k][m]
    __shared__ float Bs[8][128];   // Bs[k][n]

    const float* A    = blockIdx.z ? A1 : A0;
    const float* W    = blockIdx.z ? W1 : W0;
    const float* bias = blockIdx.z ? bias1 : bias0;
    float*       C    = blockIdx.z ? C1 : C0;

    const int tid = threadIdx.x;
    const int bm = blockIdx.y * 128;
    const int bn = blockIdx.x * 128;
    const int tx = tid & 15;
    const int ty = tid >> 4;

    const int arow = tid >> 1;
    const int ac4  = (tid & 1) << 2;
    const int brow = tid >> 5;
    const int bc4  = (tid & 31) << 2;

    const float* Ap = A + (size_t)(bm + arow) * DMODEL + ac4;
    const float* Wp = W + (size_t)brow * DMODEL + (bn + bc4);

    unsigned long long acc2[8][4];
#pragma unroll
    for (int i = 0; i < 8; i++)
#pragma unroll
        for (int j = 0; j < 4; j++) acc2[i][j] = 0ull;

    float4 av = *(const float4*)Ap;
    float4 bv = *(const float4*)Wp;

    for (int kt = 0; kt < DMODEL / 8; kt++) {
        __syncthreads();
        As[ac4 + 0][arow] = av.x;
        As[ac4 + 1][arow] = av.y;
        As[ac4 + 2][arow] = av.z;
        As[ac4 + 3][arow] = av.w;
        *(float4*)&Bs[brow][bc4] = bv;
        __syncthreads();

        if (kt + 1 < DMODEL / 8) {   // register prefetch of next tile
            av = *(const float4*)(Ap + (kt + 1) * 8);
            bv = *(const float4*)(Wp + (size_t)(kt + 1) * 8 * DMODEL);
        }

#pragma unroll
        for (int k = 0; k < 8; k++) {
            float a[8];
            *(float4*)&a[0] = *(const float4*)&As[k][ty * 8];
            *(float4*)&a[4] = *(const float4*)&As[k][ty * 8 + 4];
            unsigned long long b2[4];
#pragma unroll
            for (int j = 0; j < 4; j++)
                b2[j] = *(const unsigned long long*)&Bs[k][2 * tx + 32 * j];
            unsigned long long a2[8];
#pragma unroll
            for (int i = 0; i < 8; i++) SPLAT2(a2[i], __float_as_uint(a[i]));
#pragma unroll
            for (int i = 0; i < 8; i++)
#pragma unroll
                for (int j = 0; j < 4; j++)
                    FMA2(acc2[i][j], a2[i], b2[j]);
        }
    }

#pragma unroll
    for (int i = 0; i < 8; i++) {
        float* crow = C + (size_t)(bm + ty * 8 + i) * DMODEL + bn;
#pragma unroll
        for (int j = 0; j < 4; j++) {
            const int col = 2 * tx + 32 * j;
            unsigned lo, hi;
            UNPK2(lo, hi, acc2[i][j]);
            float2 o;
            o.x = __uint_as_float(lo) + bias[bn + col];
            o.y = __uint_as_float(hi) + bias[bn + col + 1];
            *(float2*)(crow + col) = o;
        }
    }
}

// ---------------------------------------------------------------------------
// Tensor-core GEMM (bf16 3-MMA split, legacy mma.sync) — V and output
// projections. Proven R2/R5.
// ---------------------------------------------------------------------------
#define GBM 128
#define GBN 128
#define GBK 32
#define GSTR 40
#define GSTAGE 20480
#define GNK (DMODEL / GBK)

#define MMA16816(c, a, b0, b1)                                               \
    asm volatile(                                                            \
        "mma.sync.aligned.m16n8k16.row.col.f32.bf16.bf16.f32 "               \
        "{%0,%1,%2,%3},{%4,%5,%6,%7},{%8,%9},{%0,%1,%2,%3};"                 \
        : "+f"(c[0]), "+f"(c[1]), "+f"(c[2]), "+f"(c[3])                     \
        : "r"(a[0]), "r"(a[1]), "r"(a[2]), "r"(a[3]), "r"(b0), "r"(b1))

#define CPA16(sdst, gsrc)                                                    \
    {                                                                        \
        uint32_t _d = (uint32_t)__cvta_generic_to_shared(sdst);              \
        asm volatile("cp.async.cg.shared.global [%0], [%1], 16;"             \
                     :: "r"(_d), "l"(gsrc));                                 \
    }

__global__ void __launch_bounds__(256, 2)
gemm_bf16x3(const __nv_bfloat16* __restrict__ Ahi,
            const __nv_bfloat16* __restrict__ Alo,
            const __nv_bfloat16* __restrict__ Bthi,
            const __nv_bfloat16* __restrict__ Btlo,
            const float* __restrict__ bias, float* __restrict__ C)
{
    extern __shared__ __nv_bfloat16 sm[];
    const int tid = threadIdx.x;
    const int lane = tid & 31;
    const int g = lane >> 2;
    const int tg = lane & 3;
    const int wid = tid >> 5;
    const int warp_m = wid >> 1;
    const int warp_n = wid & 1;
    const int bm = blockIdx.y * GBM;
    const int bn = blockIdx.x * GBN;

    float acc[2][8][4];
#pragma unroll
    for (int mt = 0; mt < 2; mt++)
#pragma unroll
        for (int nt = 0; nt < 8; nt++)
#pragma unroll
            for (int j = 0; j < 4; j++) acc[mt][nt][j] = 0.0f;

    const int ld_row = tid >> 2;
    const int ld_q   = tid & 3;

    const __nv_bfloat16* gAh = Ahi + (size_t)bm * DMODEL;
    const __nv_bfloat16* gAl = Alo + (size_t)bm * DMODEL;
    const __nv_bfloat16* gBh = Bthi + (size_t)bn * DMODEL;
    const __nv_bfloat16* gBl = Btlo + (size_t)bn * DMODEL;

    auto issue_stage = [&](int kt) {
        const int k0 = kt * GBK;
        __nv_bfloat16* base = sm + (kt & 1) * GSTAGE;
#pragma unroll
        for (int cc = 0; cc < 2; cc++) {
            const int row = ld_row + cc * 64;
            const int soff = row * GSTR + ld_q * 8;
            const size_t goff = (size_t)row * DMODEL + k0 + ld_q * 8;
            CPA16(base + soff,         gAh + goff);
            CPA16(base + 5120 + soff,  gAl + goff);
            CPA16(base + 10240 + soff, gBh + goff);
            CPA16(base + 15360 + soff, gBl + goff);
        }
        asm volatile("cp.async.commit_group;");
    };

    issue_stage(0);

    for (int kt = 0; kt < GNK; kt++) {
        asm volatile("cp.async.wait_group 0;" ::: "memory");
        __syncthreads();
        if (kt + 1 < GNK) issue_stage(kt + 1);

        const __nv_bfloat16* sa_hi = sm + (kt & 1) * GSTAGE;
        const __nv_bfloat16* sa_lo = sa_hi + 5120;
        const __nv_bfloat16* sb_hi = sa_hi + 10240;
        const __nv_bfloat16* sb_lo = sa_hi + 15360;

#pragma unroll
        for (int ks = 0; ks < 2; ks++) {
            const int kb = ks * 16 + tg * 2;
            uint32_t ah[2][4], al[2][4];
#pragma unroll
            for (int mt = 0; mt < 2; mt++) {
                const int r = warp_m * 32 + mt * 16 + g;
                const __nv_bfloat16* pa = sa_hi + r * GSTR + kb;
                ah[mt][0] = *(const uint32_t*)(pa);
                ah[mt][1] = *(const uint32_t*)(pa + 8 * GSTR);
                ah[mt][2] = *(const uint32_t*)(pa + 8);
                ah[mt][3] = *(const uint32_t*)(pa + 8 * GSTR + 8);
                const __nv_bfloat16* pl = sa_lo + r * GSTR + kb;
                al[mt][0] = *(const uint32_t*)(pl);
                al[mt][1] = *(const uint32_t*)(pl + 8 * GSTR);
                al[mt][2] = *(const uint32_t*)(pl + 8);
                al[mt][3] = *(const uint32_t*)(pl + 8 * GSTR + 8);
            }
#pragma unroll
            for (int nt = 0; nt < 8; nt++) {
                const int n = warp_n * 64 + nt * 8 + g;
                const __nv_bfloat16* pb = sb_hi + n * GSTR + kb;
                uint32_t bh0 = *(const uint32_t*)(pb);
                uint32_t bh1 = *(const uint32_t*)(pb + 8);
                const __nv_bfloat16* pbl = sb_lo + n * GSTR + kb;
                uint32_t bl0 = *(const uint32_t*)(pbl);
                uint32_t bl1 = *(const uint32_t*)(pbl + 8);
#pragma unroll
                for (int mt = 0; mt < 2; mt++) {
                    MMA16816(acc[mt][nt], ah[mt], bh0, bh1);
                    MMA16816(acc[mt][nt], ah[mt], bl0, bl1);
                    MMA16816(acc[mt][nt], al[mt], bh0, bh1);
                }
            }
        }
    }

#pragma unroll
    for (int mt = 0; mt < 2; mt++) {
        const int r0 = bm + warp_m * 32 + mt * 16 + g;
#pragma unroll
        for (int nt = 0; nt < 8; nt++) {
            const int col = bn + warp_n * 64 + nt * 8 + tg * 2;
            const float bx = bias[col];
            const float by = bias[col + 1];
            float2 v0 = make_float2(acc[mt][nt][0] + bx, acc[mt][nt][1] + by);
            float2 v1 = make_float2(acc[mt][nt][2] + bx, acc[mt][nt][3] + by);
            *(float2*)&C[(size_t)r0 * DMODEL + col] = v0;
            *(float2*)&C[(size_t)(r0 + 8) * DMODEL + col] = v1;
        }
    }
}

// ---------------------------------------------------------------------------
// Sparse causal attention, R16: AT_ROWS=32 with 256-thread blocks (8 warps
// x 4 rows/warp) — each K tile now serves 32 rows, halving loader phases,
// K gmem traffic, q-load work and sync count PER ROW vs R14. Score-loop
// phases per row unchanged. smem = 48KB static (ks 32KB + qs2 16KB), occ 2.
// Scale 0.125 folded into q (bitwise-identical scores).
// ---------------------------------------------------------------------------
#define AT_ROWS 32
#define KTILE   128
#define KPAD    128
#define MAXK    5
#define NEGINF  (-CUDART_INF_F)

__global__ void __launch_bounds__(256, 2)
attn_sparse(const float* __restrict__ Q, const float* __restrict__ K,
            const float* __restrict__ V, const int* __restrict__ kidx_p,
            float* __restrict__ O)
{
    __shared__ float ks[DKH][KPAD];        // 32 KB transposed K tile
    __shared__ float qs2[AT_ROWS][128];    // 16 KB duplicated q rows

    const int bh = blockIdx.y;
    const int b  = bh >> 3;
    const int h  = bh & 7;
    const int row_base = blockIdx.x * AT_ROWS;
    const int tid  = threadIdx.x;          // 0..255
    const int wid  = tid >> 5;             // 0..7
    const int lane = tid & 31;
    const int kk   = *kidx_p;

    const size_t base = ((size_t)b * SEQ) * DMODEL + (size_t)h * DKH;

    // load q rows (pre-scaled by 0.125), duplicated
    for (int i = tid; i < AT_ROWS * DKH; i += 256) {
        const int rr = i >> 6, d = i & 63;
        const float qv =
            Q[base + (size_t)(row_base + rr) * DMODEL + d] * 0.125f;
        unsigned long long q2;
        SPLAT2(q2, __float_as_uint(qv));
        *(unsigned long long*)&qs2[rr][2 * d] = q2;
    }

    const int nkeys = row_base + AT_ROWS - 1;   // strictly-causal: keys j < r
    const int lr0 = wid * 4;                    // 4 rows per warp

    // loader mapping: key = tid&127, d-half = tid>>7 (conflict-free STS)
    const int ld_key  = tid & 127;
    const int ld_half = tid >> 7;               // 0 or 1

    unsigned long long sc2[4][8];
#pragma unroll
    for (int rr = 0; rr < 4; rr++)
#pragma unroll
        for (int p = 0; p < 8; p++) sc2[rr][p] = 0ull;

    // ---- score pass: QK^T over key tiles ----
#pragma unroll
    for (int tt = 0; tt < 4; tt++) {
        const int t0k = tt << 7;
        if (t0k >= nkeys) break;
        const int tl = min(KTILE, nkeys - t0k);
        __syncthreads();
        // loader: 256 threads, each owns key=ld_key and 32 d-values
        {
            const float* krow = &K[base + (size_t)(t0k + ld_key) * DMODEL +
                                   ld_half * 32];
            const bool ok = ld_key < tl;
#pragma unroll
            for (int p = 0; p < 8; p++) {
                const int d4 = ld_half * 32 + (p << 2);
                float4 kv = ok ? *(const float4*)(krow + (p << 2))
                               : make_float4(0.f, 0.f, 0.f, 0.f);
                ks[d4 + 0][ld_key] = kv.x;
                ks[d4 + 1][ld_key] = kv.y;
                ks[d4 + 2][ld_key] = kv.z;
                ks[d4 + 3][ld_key] = kv.w;
            }
        }
        __syncthreads();
#pragma unroll 4
        for (int d = 0; d < DKH; d += 2) {
            const ulonglong2 kva = *(const ulonglong2*)&ks[d][lane << 2];
            const ulonglong2 kvb = *(const ulonglong2*)&ks[d + 1][lane << 2];
#pragma unroll
            for (int rr = 0; rr < 4; rr++) {
                const ulonglong2 qp =
                    *(const ulonglong2*)&qs2[lr0 + rr][2 * d]; // {qd,qd+1}dup
                FMA2(sc2[rr][tt * 2 + 0], qp.x, kva.x);
                FMA2(sc2[rr][tt * 2 + 1], qp.x, kva.y);
                FMA2(sc2[rr][tt * 2 + 0], qp.y, kvb.x);
                FMA2(sc2[rr][tt * 2 + 1], qp.y, kvb.y);
            }
        }
    }

    // ---- per row-pair: unpack, mask, REDUX top-k, streamed PV ----
#pragma unroll
    for (int pp = 0; pp < 2; pp++) {
        const int r0g = row_base + lr0 + pp * 2;
        const int r1g = r0g + 1;

        float sc[2][16];
#pragma unroll
        for (int q2i = 0; q2i < 2; q2i++)
#pragma unroll
            for (int p = 0; p < 8; p++) {
                unsigned lo, hi;
                UNPK2(lo, hi, sc2[pp * 2 + q2i][p]);
                sc[q2i][p * 2]     = __uint_as_float(lo);
                sc[q2i][p * 2 + 1] = __uint_as_float(hi);
            }

        // mask invalid keys (scale already folded into q)
#pragma unroll
        for (int rr = 0; rr < 2; rr++) {
            const int r = r0g + rr;
#pragma unroll
            for (int s = 0; s < 16; s++) {
                const int j = ((s >> 2) << 7) + (lane << 2) + (s & 3);
                if (j >= r) sc[rr][s] = NEGINF;
            }
        }

        // extraction: nex = min(r, kk) warp maxima per row
        const int nex0 = min(r0g, kk);
        const int nex1 = min(r1g, kk);
        const int nexm = min(max(nex0, nex1), MAXK);

        float lm0 = NEGINF, lm1 = NEGINF;
        int   sl0 = 0, sl1 = 0;
        unsigned rem0 = 0, rem1 = 0;
#pragma unroll
        for (int s = 0; s < 16; s++) {
            if (sc[0][s] > lm0) { lm0 = sc[0][s]; sl0 = s; }
            if (sc[1][s] > lm1) { lm1 = sc[1][s]; sl1 = s; }
        }

        float ev0[MAXK], ev1[MAXK];
        int   ej0[MAXK], ej1[MAXK];
#pragma unroll
        for (int e = 0; e < MAXK; e++) {
            ev0[e] = NEGINF; ev1[e] = NEGINF; ej0[e] = 0; ej1[e] = 0;
        }

#pragma unroll
        for (int e = 0; e < MAXK; e++) {
            if (e < nexm) {
                const uint32_t u0 = ford(lm0);
                const uint32_t u1 = ford(lm1);
                const uint32_t mx0 = __reduce_max_sync(0xffffffffu, u0);
                const uint32_t mx1 = __reduce_max_sync(0xffffffffu, u1);
                const unsigned bl0 = __ballot_sync(0xffffffffu, u0 == mx0);
                const unsigned bl1 = __ballot_sync(0xffffffffu, u1 == mx1);
                const int own0 = __ffs(bl0) - 1;
                const int own1 = __ffs(bl1) - 1;
                ev0[e] = ford_inv(mx0);
                ev1[e] = ford_inv(mx1);
                const int jid0 = ((sl0 >> 2) << 7) + (lane << 2) + (sl0 & 3);
                const int jid1 = ((sl1 >> 2) << 7) + (lane << 2) + (sl1 & 3);
                ej0[e] = __shfl_sync(0xffffffffu, jid0, own0);
                ej1[e] = __shfl_sync(0xffffffffu, jid1, own1);
                if (lane == own0) {
                    rem0 |= 1u << sl0;
                    lm0 = NEGINF; sl0 = 0;
#pragma unroll
                    for (int s = 0; s < 16; s++) {
                        const float v = ((rem0 >> s) & 1u) ? NEGINF : sc[0][s];
                        if (v > lm0) { lm0 = v; sl0 = s; }
                    }
                }
                if (lane == own1) {
                    rem1 |= 1u << sl1;
                    lm1 = NEGINF; sl1 = 0;
#pragma unroll
                    for (int s = 0; s < 16; s++) {
                        const float v = ((rem1 >> s) & 1u) ? NEGINF : sc[1][s];
                        if (v > lm1) { lm1 = v; sl1 = s; }
                    }
                }
            }
        }

        // inline weights + streamed PV (no staging arrays)
        const float m0 = (nex0 > 0) ? ev0[0] : 0.f;
        const float m1 = (nex1 > 0) ? ev1[0] : 0.f;
        float ksum0 = 0.f, ksum1 = 0.f;
#pragma unroll
        for (int e = 0; e < MAXK; e++) {
            if (e < nex0) ksum0 += __expf(ev0[e] - m0);
            if (e < nex1) ksum1 += __expf(ev1[e] - m1);
        }
        const float inv0 = (nex0 > 0) ? 1.0f / ksum0 : 0.f;
        const float inv1 = (nex1 > 0) ? 1.0f / ksum1 : 0.f;

        float o00 = 0.f, o01 = 0.f, o10 = 0.f, o11 = 0.f;
#pragma unroll
        for (int e = 0; e < MAXK; e++) {
            const float w0 = (e < nex0) ? __expf(ev0[e] - m0) * inv0 : 0.f;
            const float w1 = (e < nex1) ? __expf(ev1[e] - m1) * inv1 : 0.f;
            const float* v0p = &V[base + (size_t)ej0[e] * DMODEL];
            const float* v1p = &V[base + (size_t)ej1[e] * DMODEL];
            if (e < nex0) {
                o00 = fmaf(w0, v0p[lane], o00);
                o01 = fmaf(w0, v0p[lane + 32], o01);
            }
            if (e < nex1) {
                o10 = fmaf(w1, v1p[lane], o10);
                o11 = fmaf(w1, v1p[lane + 32], o11);
            }
        }

        O[base + (size_t)r0g * DMODEL + lane]      = o00;
        O[base + (size_t)r0g * DMODEL + lane + 32] = o01;
        O[base + (size_t)r1g * DMODEL + lane]      = o10;
        O[base + (size_t)r1g * DMODEL + lane + 32] = o11;
    }
}

// ---------------------------------------------------------------------------
extern "C" void kernel_launch(void* const* d_in, const int* in_sizes, int n_in,
                              void* d_out, int out_size)
{
    const float* q   = (const float*)d_in[0];
    const float* k   = (const float*)d_in[1];
    const float* v   = (const float*)d_in[2];
    const float* w_q = (const float*)d_in[3];
    const float* b_q = (const float*)d_in[4];
    const float* w_k = (const float*)d_in[5];
    const float* b_k = (const float*)d_in[6];
    const float* w_v = (const float*)d_in[7];
    const float* b_v = (const float*)d_in[8];
    const float* w_o = (const float*)d_in[9];
    const float* b_o = (const float*)d_in[10];
    const int*   kid = (const int*)d_in[11];
    float* out = (float*)d_out;

    float *Qp, *Kp, *Vp, *AO;
    __nv_bfloat16 *Ahi, *Alo, *Wthi, *Wtlo;
    cudaGetSymbolAddress((void**)&Qp, g_Qp);
    cudaGetSymbolAddress((void**)&Kp, g_Kp);
    cudaGetSymbolAddress((void**)&Vp, g_Vp);
    cudaGetSymbolAddress((void**)&AO, g_AO);
    cudaGetSymbolAddress((void**)&Ahi, g_Ahi);
    cudaGetSymbolAddress((void**)&Alo, g_Alo);
    cudaGetSymbolAddress((void**)&Wthi, g_Wthi);
    cudaGetSymbolAddress((void**)&Wtlo, g_Wtlo);

    cudaFuncSetAttribute(gemm_bf16x3,
                         cudaFuncAttributeMaxDynamicSharedMemorySize,
                         2 * GSTAGE * (int)sizeof(__nv_bfloat16));

    const int n4 = MROWS * DMODEL / 4;
    const int cfblk = 256 + (n4 + 255) / 256;     // fused conv grid
    dim3 ggrid(DMODEL / GBN, MROWS / GBM);        // (4, 128)
    dim3 ggrid_qk(DMODEL / 128, MROWS / 128, 2);  // Q and K in one launch
    const int smem = 2 * GSTAGE * (int)sizeof(__nv_bfloat16);

    // 1) V conversion path (weights + activations fused).
    conv_fused<<<cfblk, 256>>>((const float4*)v, w_v,
                               (uint2*)Ahi, (uint2*)Alo, Wthi, Wtlo, n4);
    // 2) V projection (tensor cores).
    gemm_bf16x3<<<ggrid, 256, smem>>>(Ahi, Alo, Wthi, Wtlo, b_v, Vp);
    // 3) Q + K projections: exact fp32 (packed f32x2 FMA), one launch.
    sgemm_bias_x2_qk<<<ggrid_qk, 256>>>(q, w_q, b_q, Qp, k, w_k, b_k, Kp);
    // 4) Attention (launch #4 — profiled slot). 256-thread, 32-row blocks.
    dim3 ga(SEQ / AT_ROWS, BATCH * HEADS); // (16, 256)
    attn_sparse<<<ga, 256>>>(Qp, Kp, Vp, kid, AO);
    // 5) Output conversion path (w_o transpose + AO split fused).
    conv_fused<<<cfblk, 256>>>((const float4*)AO, w_o,
                               (uint2*)Ahi, (uint2*)Alo, Wthi, Wtlo, n4);
    // 6) Output projection.
    gemm_bf16x3<<<ggrid, 256, smem>>>(Ahi, Alo, Wthi, Wtlo, b_o, out);
}